// round 14
// baseline (speedup 1.0000x reference)
#include <cuda_runtime.h>
#include <cuda_bf16.h>

#define BB    64
#define LL    4096
#define DD    256
#define VOCAB 33

// ---- K1 (unchanged from R7: proven) ----
#define NT1         512
#define NWARP1      16
#define HIST_BLOCKS 128          // 64 rows x 2 halves (2048 tokens each)
#define M1_BLOCKS   66           // 33 v x 2 col-halves
#define GRID1       (HIST_BLOCKS + M1_BLOCKS)

// ---- K2: occupancy-first ----
#define NT2   512
#define CT2   32                 // cols per block tile
#define GRID2 (BB * (DD / CT2))  // 64 x 8 = 512 blocks

__device__ int   gpart[HIST_BLOCKS][VOCAB];  // per-block histogram partials (overwritten)
__device__ float g_M1[VOCAB * DD];           // emb @ W1 (overwritten)

// ============ K1: histograms (blocks 0-127) + M1 = emb@W1 (blocks 128-193) ============
__global__ __launch_bounds__(NT1)
void k1_hist_m1(const int* __restrict__ X,
                const int* __restrict__ vlen,
                const float* __restrict__ emb,
                const float* __restrict__ W1)
{
    __shared__ int   wh[NWARP1][VOCAB];
    __shared__ float embs[DD];
    __shared__ alignas(16) float m1part[4][128];

    const int bid  = blockIdx.x;
    const int tid  = threadIdx.x;
    const int warp = tid >> 5;

    if (bid < HIST_BLOCKS) {
        const int row  = bid >> 1;
        const int half = bid & 1;
        const int vl   = vlen[row];
        const int l0   = half * 2048 + tid * 4;

        if (half * 2048 >= vl) {
            if (tid < VOCAB) gpart[bid][tid] = 0;
            return;
        }
        for (int i = tid; i < NWARP1 * VOCAB; i += NT1)
            (&wh[0][0])[i] = 0;
        __syncthreads();

        if (l0 < vl) {
            int4 xv = ((const int4*)X)[row * (LL / 4) + half * 512 + tid];
            atomicAdd(&wh[warp][xv.x], 1);
            if (l0 + 1 < vl) atomicAdd(&wh[warp][xv.y], 1);
            if (l0 + 2 < vl) atomicAdd(&wh[warp][xv.z], 1);
            if (l0 + 3 < vl) atomicAdd(&wh[warp][xv.w], 1);
        }
        __syncthreads();

        if (tid < VOCAB) {
            int s = 0;
            #pragma unroll
            for (int w = 0; w < NWARP1; w++) s += wh[w][tid];
            gpart[bid][tid] = s;
        }
    } else {
        // M1[v][128*ch .. +128) = emb[v] @ W1[:, cols]
        const int j  = bid - HIST_BLOCKS;
        const int v  = j >> 1;
        const int ch = j & 1;

        if (tid < DD) embs[tid] = emb[v * DD + tid];
        __syncthreads();

        const int c   = tid & 127;
        const int g   = tid >> 7;
        const int col = ch * 128 + c;

        float acc = 0.0f;
        #pragma unroll 8
        for (int kk = 0; kk < 64; kk++) {
            const int k = g * 64 + kk;
            acc = fmaf(embs[k], W1[k * DD + col], acc);
        }
        m1part[g][c] = acc;
        __syncthreads();

        if (tid < 128)
            g_M1[v * DD + ch * 128 + tid] =
                m1part[0][tid] + m1part[1][tid] + m1part[2][tid] + m1part[3][tid];
    }
}

// ============ K2: 512 blocks x 512 thr; per (row, 32-col tile) ============
__global__ __launch_bounds__(NT2)
void k2_mlp(const float* __restrict__ b1,
            const float* __restrict__ W2,
            const float* __restrict__ b2,
            float* __restrict__ out)
{
    __shared__ float cnt_s[VOCAB];
    __shared__ alignas(16) float  hpart[2][DD];
    __shared__ alignas(16) float  h_s[DD];
    __shared__ alignas(16) float4 part[64][8];   // [k-group][float4-col] 8 KB
    __shared__ alignas(16) float4 p2[16][8];     // stage-2 partials

    const int r   = (int)blockIdx.x >> 3;        // batch row
    const int ct  = (int)blockIdx.x & 7;         // 32-col tile
    const int tid = threadIdx.x;

    if (tid < VOCAB)
        cnt_s[tid] = (float)(gpart[2 * r][tid] + gpart[2 * r + 1][tid]);
    __syncthreads();

    // ---- h: 2-way vocab split, 17 independent L2-hot loads max ----
    {
        const int d = tid & 255;
        const int q = tid >> 8;                  // 0: v 0..16, 1: v 17..32
        float a = (q == 0) ? b1[d] : 0.0f;
        const int v0 = q ? 17 : 0;
        const int v1 = q ? 33 : 17;
        #pragma unroll
        for (int v = v0; v < v1; v++)
            a = fmaf(cnt_s[v], g_M1[v * DD + d], a);
        hpart[q][d] = a;
    }
    __syncthreads();
    if (tid < DD)
        h_s[tid] = fmaxf(hpart[0][tid] + hpart[1][tid], 0.0f);
    __syncthreads();

    // ---- layer 2: 64-way split-K (4 k each) x 8 float4-cols; 4 LDG.128/thread ----
    {
        const int kg = tid >> 3;                 // 0..63
        const int f4 = tid & 7;                  // float4 col in tile
        const int cf4 = ct * 8 + f4;
        const float4* W2v = (const float4*)W2;

        float4 acc = make_float4(0.f, 0.f, 0.f, 0.f);
        #pragma unroll
        for (int kk = 0; kk < 4; kk++) {         // 4 independent loads
            const int   k = kg * 4 + kk;
            const float s = h_s[k];
            const float4 w = W2v[k * (DD / 4) + cf4];
            acc.x = fmaf(s, w.x, acc.x);
            acc.y = fmaf(s, w.y, acc.y);
            acc.z = fmaf(s, w.z, acc.z);
            acc.w = fmaf(s, w.w, acc.w);
        }
        part[kg][f4] = acc;
    }
    __syncthreads();

    // ---- 2-stage reduction of 64 k-groups ----
    if (tid < 128) {
        const int f4  = tid & 7;
        const int seg = tid >> 3;                // 0..15, sums 4 k-groups
        float4 s = make_float4(0.f, 0.f, 0.f, 0.f);
        #pragma unroll
        for (int j = 0; j < 4; j++) {
            const float4 p = part[seg * 4 + j][f4];
            s.x += p.x; s.y += p.y; s.z += p.z; s.w += p.w;
        }
        p2[seg][f4] = s;
    }
    __syncthreads();

    if (tid < 8) {
        float4 s = make_float4(0.f, 0.f, 0.f, 0.f);
        #pragma unroll
        for (int seg = 0; seg < 16; seg++) {
            const float4 p = p2[seg][tid];
            s.x += p.x; s.y += p.y; s.z += p.z; s.w += p.w;
        }
        const float4 bb = ((const float4*)b2)[ct * 8 + tid];
        s.x = fmaxf(s.x + bb.x, 0.f);
        s.y = fmaxf(s.y + bb.y, 0.f);
        s.z = fmaxf(s.z + bb.z, 0.f);
        s.w = fmaxf(s.w + bb.w, 0.f);
        *((float4*)&out[r * DD + ct * 32 + 4 * tid]) = s;
    }
}

extern "C" void kernel_launch(void* const* d_in, const int* in_sizes, int n_in,
                              void* d_out, int out_size)
{
    const int*   X    = (const int*)d_in[0];
    const int*   vlen = (const int*)d_in[1];
    const float* emb  = (const float*)d_in[2];
    const float* W1   = (const float*)d_in[3];
    const float* b1   = (const float*)d_in[4];
    const float* W2   = (const float*)d_in[5];
    const float* b2   = (const float*)d_in[6];
    float*       out  = (float*)d_out;

    k1_hist_m1<<<GRID1, NT1>>>(X, vlen, emb, W1);
    k2_mlp<<<GRID2, NT2>>>(b1, W2, b2, out);
}

// round 15
// speedup vs baseline: 1.1463x; 1.1463x over previous
#include <cuda_runtime.h>
#include <cuda_bf16.h>
#include <cooperative_groups.h>
namespace cg = cooperative_groups;

#define BB    64
#define LL    4096
#define DD    256
#define VOCAB 33
#define NT    512
#define NWARP 16
#define GRID  196     // A: 64 hist + 132 M1 ; B: 128 tiles (16 rowG x 8 colG)

__device__ int   gcnt[BB][VOCAB];
__device__ float g_M1[VOCAB * DD];

__global__ __launch_bounds__(NT, 2)
void prot_net_coop(const int* __restrict__ X,
                   const int* __restrict__ vlen,
                   const float* __restrict__ emb,
                   const float* __restrict__ W1,
                   const float* __restrict__ b1,
                   const float* __restrict__ W2,
                   const float* __restrict__ b2,
                   float* __restrict__ out)
{
    __shared__ union SMem {
        struct { int wh[NWARP][VOCAB]; } a;                // hist
        struct {                                           // M1 tile
            float  embs[DD];
            float4 part[32][16];                           // [kg][f4c] 8 KB
        } m;
        struct {                                           // phase B
            float  cnt[4][VOCAB];
            float  h[4][DD];                               // 4 KB
            float4 part[16][4][8];                         // [kg][row][f4c] 8 KB
        } b;
    } sm;

    const int bid = blockIdx.x;
    const int tid = threadIdx.x;

    // ================= PHASE A =================
    if (bid < 64) {
        // ---- full-row histogram (R10-proven) ----
        const int warp = tid >> 5;
        const int row  = bid;
        const int4 xa = ((const int4*)X)[row * (LL / 4) + tid];
        const int4 xb = ((const int4*)X)[row * (LL / 4) + 512 + tid];
        const int  vl = vlen[row];
        const int  la = tid * 4;
        const int  lb = 2048 + tid * 4;

        for (int i = tid; i < NWARP * VOCAB; i += NT)
            (&sm.a.wh[0][0])[i] = 0;
        __syncthreads();

        if (la < vl) {
            atomicAdd(&sm.a.wh[warp][xa.x], 1);
            if (la + 1 < vl) atomicAdd(&sm.a.wh[warp][xa.y], 1);
            if (la + 2 < vl) atomicAdd(&sm.a.wh[warp][xa.z], 1);
            if (la + 3 < vl) atomicAdd(&sm.a.wh[warp][xa.w], 1);
        }
        if (lb < vl) {
            atomicAdd(&sm.a.wh[warp][xb.x], 1);
            if (lb + 1 < vl) atomicAdd(&sm.a.wh[warp][xb.y], 1);
            if (lb + 2 < vl) atomicAdd(&sm.a.wh[warp][xb.z], 1);
            if (lb + 3 < vl) atomicAdd(&sm.a.wh[warp][xb.w], 1);
        }
        __syncthreads();

        if (tid < VOCAB) {
            int s = 0;
            #pragma unroll
            for (int w = 0; w < NWARP; w++) s += sm.a.wh[w][tid];
            gcnt[row][tid] = s;
        }
        __syncthreads();
    } else {
        // ---- M1[v][64*cq .. +64) = emb[v] @ W1[:, cols] ; W1 tile = 64 KB ----
        const int j  = bid - 64;              // 0..131
        const int v  = j >> 2;                // 0..32
        const int cq = j & 3;                 // col quarter

        if (tid < DD) sm.m.embs[tid] = emb[v * DD + tid];
        __syncthreads();

        const int f4 = tid & 15;              // float4 col in quarter (16 = 64 cols)
        const int kg = tid >> 4;              // k-group 0..31 (8 k each)
        const float4* W1v = (const float4*)W1;

        float4 acc = make_float4(0.f, 0.f, 0.f, 0.f);
        #pragma unroll
        for (int kk = 0; kk < 8; kk++) {      // 8 independent LDG.128
            const int   k = kg * 8 + kk;
            const float e = sm.m.embs[k];
            const float4 w = W1v[k * (DD / 4) + cq * 16 + f4];
            acc.x = fmaf(e, w.x, acc.x);
            acc.y = fmaf(e, w.y, acc.y);
            acc.z = fmaf(e, w.z, acc.z);
            acc.w = fmaf(e, w.w, acc.w);
        }
        sm.m.part[kg][f4] = acc;
        __syncthreads();

        if (tid < 64) {
            const int f = tid >> 2, el = tid & 3;
            float s = 0.f;
            #pragma unroll
            for (int g = 0; g < 32; g++)
                s += ((const float*)&sm.m.part[g][f])[el];
            g_M1[v * DD + cq * 64 + f * 4 + el] = s;
        }
        __syncthreads();
    }

    // ================= GRID BARRIER (all blocks arrive; no early returns) =====
    cg::this_grid().sync();

    // ================= PHASE B: 4-row x 32-col tiles, blocks 0..127 =========
    if (bid < 128) {
        const int r0 = (bid >> 3) * 4;        // 4 rows
        const int cg_ = bid & 7;              // col group
        const int c0 = cg_ * 32;

        if (tid < 4 * VOCAB) {
            const int r = tid / VOCAB, v = tid % VOCAB;
            sm.b.cnt[r][v] = (float)gcnt[r0 + r][v];
        }
        __syncthreads();

        // ---- h for 4 rows: thread (d, rh) does rows 2rh, 2rh+1; 33 loads ----
        {
            const int d  = tid & 255;
            const int rh = tid >> 8;
            const float bb = b1[d];
            float a0 = 0.f, a1 = 0.f;
            #pragma unroll
            for (int v = 0; v < VOCAB; v++) {
                const float m = g_M1[v * DD + d];          // coalesced, L1-shared
                a0 = fmaf(sm.b.cnt[2 * rh + 0][v], m, a0);
                a1 = fmaf(sm.b.cnt[2 * rh + 1][v], m, a1);
            }
            sm.b.h[2 * rh + 0][d] = fmaxf(a0 + bb, 0.f);
            sm.b.h[2 * rh + 1][d] = fmaxf(a1 + bb, 0.f);
        }
        __syncthreads();

        // ---- layer 2: W2 tile 32 KB, reused across 4 rows ----
        {
            const int kg   = tid >> 5;        // 0..15 (16 k each)
            const int lane = tid & 31;
            const int rq   = lane >> 3;       // row 0..3
            const int f4c  = lane & 7;        // float4 col in tile
            const int cf4  = cg_ * 8 + f4c;
            const float4* W2v = (const float4*)W2;

            float4 acc = make_float4(0.f, 0.f, 0.f, 0.f);
            #pragma unroll
            for (int kk = 0; kk < 16; kk++) {
                const int k = kg * 16 + kk;
                const float4 w = W2v[k * (DD / 4) + cf4];  // 8 distinct/warp, L1-reused
                const float  s = sm.b.h[rq][k];
                acc.x = fmaf(s, w.x, acc.x);
                acc.y = fmaf(s, w.y, acc.y);
                acc.z = fmaf(s, w.z, acc.z);
                acc.w = fmaf(s, w.w, acc.w);
            }
            sm.b.part[kg][rq][f4c] = acc;
        }
        __syncthreads();

        // ---- reduce 16 k-groups, bias+relu, store ----
        if (tid < 128) {
            const int r = tid >> 5, c = tid & 31;
            float s = b2[c0 + c];
            #pragma unroll
            for (int g = 0; g < 16; g++)
                s += ((const float*)&sm.b.part[g][r][c >> 2])[c & 3];
            out[(r0 + r) * DD + c0 + c] = fmaxf(s, 0.f);
        }
    }
}

extern "C" void kernel_launch(void* const* d_in, const int* in_sizes, int n_in,
                              void* d_out, int out_size)
{
    const int*   X    = (const int*)d_in[0];
    const int*   vlen = (const int*)d_in[1];
    const float* emb  = (const float*)d_in[2];
    const float* W1   = (const float*)d_in[3];
    const float* b1   = (const float*)d_in[4];
    const float* W2   = (const float*)d_in[5];
    const float* b2   = (const float*)d_in[6];
    float*       out  = (float*)d_out;

    void* args[] = { (void*)&X, (void*)&vlen, (void*)&emb, (void*)&W1,
                     (void*)&b1, (void*)&W2, (void*)&b2, (void*)&out };
    cudaLaunchCooperativeKernel((void*)prot_net_coop,
                                dim3(GRID), dim3(NT), args, 0, (cudaStream_t)0);
}

// round 16
// speedup vs baseline: 1.1963x; 1.0436x over previous
#include <cuda_runtime.h>
#include <cuda_bf16.h>
#include <cooperative_groups.h>
namespace cg = cooperative_groups;

#define BB    64
#define LL    4096
#define DD    256
#define VOCAB 33
#define VPAD  40                  // vocab padded to 8 groups of 5

#define NT          512
#define NWARP       16
#define HIST_BLOCKS 64            // one full row per block
#define M1_BASE     HIST_BLOCKS
#define M1_BLOCKS   66            // 33 v x 2 col-halves
#define GRID        130           // <= 148 SMs at occ 1

__device__ int    gcnt[BB][VOCAB];
__device__ float4 g_M1[VPAD * (DD / 4)];   // rows 33..39 never written -> stay 0

__global__ __launch_bounds__(NT, 1)
void prot_net_coop(const int* __restrict__ X,
                   const int* __restrict__ vlen,
                   const float* __restrict__ emb,
                   const float* __restrict__ W1,
                   const float* __restrict__ b1,
                   const float* __restrict__ W2,
                   const float* __restrict__ b2,
                   float* __restrict__ out)
{
    __shared__ int   wh[NWARP][VOCAB];
    __shared__ float embs[DD];
    __shared__ alignas(16) float4 m1part[16][32];
    __shared__ float cnt_s[VPAD];
    __shared__ alignas(16) float4 hp[8][64];     // h partials
    __shared__ alignas(16) float  h_s[DD];
    __shared__ alignas(16) float4 p2[16][32];    // layer-2 partials

    const int bid  = blockIdx.x;
    const int tid  = threadIdx.x;
    const int warp = tid >> 5;

    // ================= PHASE A =================
    if (bid < HIST_BLOCKS) {
        const int row = bid;
        const int4 xa = ((const int4*)X)[row * (LL / 4) + tid];
        const int4 xb = ((const int4*)X)[row * (LL / 4) + 512 + tid];
        const int  vl = vlen[row];
        const int  la = tid * 4;
        const int  lb = 2048 + tid * 4;

        for (int i = tid; i < NWARP * VOCAB; i += NT)
            (&wh[0][0])[i] = 0;
        __syncthreads();

        if (la < vl) {
            atomicAdd(&wh[warp][xa.x], 1);
            if (la + 1 < vl) atomicAdd(&wh[warp][xa.y], 1);
            if (la + 2 < vl) atomicAdd(&wh[warp][xa.z], 1);
            if (la + 3 < vl) atomicAdd(&wh[warp][xa.w], 1);
        }
        if (lb < vl) {
            atomicAdd(&wh[warp][xb.x], 1);
            if (lb + 1 < vl) atomicAdd(&wh[warp][xb.y], 1);
            if (lb + 2 < vl) atomicAdd(&wh[warp][xb.z], 1);
            if (lb + 3 < vl) atomicAdd(&wh[warp][xb.w], 1);
        }
        __syncthreads();

        if (tid < VOCAB) {
            int s = 0;
            #pragma unroll
            for (int w = 0; w < NWARP; w++) s += wh[w][tid];
            gcnt[row][tid] = s;
        }
    } else {
        const int j  = bid - M1_BASE;          // 0..65
        const int v  = j >> 1;
        const int ch = j & 1;

        if (tid < DD) embs[tid] = emb[v * DD + tid];
        __syncthreads();

        const int f4c = tid & 31;
        const int g   = tid >> 5;              // 16 k-groups
        const float4* W1v = (const float4*)W1;

        float4 acc = make_float4(0.f, 0.f, 0.f, 0.f);
        #pragma unroll
        for (int kk = 0; kk < 16; kk++) {      // 16 independent LDG.128
            const int   k = g * 16 + kk;
            const float e = embs[k];
            const float4 w = W1v[k * (DD / 4) + ch * 32 + f4c];
            acc.x = fmaf(e, w.x, acc.x);
            acc.y = fmaf(e, w.y, acc.y);
            acc.z = fmaf(e, w.z, acc.z);
            acc.w = fmaf(e, w.w, acc.w);
        }
        m1part[g][f4c] = acc;
        __syncthreads();

        if (tid < 32) {
            float4 s = make_float4(0.f, 0.f, 0.f, 0.f);
            #pragma unroll
            for (int g2 = 0; g2 < 16; g2++) {
                const float4 p = m1part[g2][tid];
                s.x += p.x; s.y += p.y; s.z += p.z; s.w += p.w;
            }
            g_M1[v * (DD / 4) + ch * 32 + tid] = s;
        }
    }

    // ================= GRID BARRIER =================
    cg::this_grid().sync();

    // ================= PHASE B: (row, 128-col half), blocks 0..127 =================
    if (bid < 128) {
        const int r    = bid >> 1;
        const int half = bid & 1;

        const int kg   = tid >> 5;             // k-group 0..15 (16 k each)
        const int lane = tid & 31;             // float4 col in half
        const int cf4  = half * 32 + lane;
        const float4* W2v = (const float4*)W2;

        // --- prefetch FIRST HALF of W2 k-slice: overlaps all h-related latency ---
        float4 w[8];
        #pragma unroll
        for (int j = 0; j < 8; j++)
            w[j] = W2v[(kg * 16 + j) * (DD / 4) + cf4];

        if (tid < VPAD)
            cnt_s[tid] = (tid < VOCAB) ? (float)gcnt[r][tid] : 0.0f;
        __syncthreads();

        // --- h = cnt @ M1 : 8 vocab-groups x 64 float4-dims ---
        {
            const int d4 = tid & 63;
            const int q  = tid >> 6;           // vocab group 0..7
            float4 a = make_float4(0.f, 0.f, 0.f, 0.f);
            #pragma unroll
            for (int j = 0; j < 5; j++) {
                const int   v = q * 5 + j;
                const float c = cnt_s[v];
                const float4 m = g_M1[v * (DD / 4) + d4];
                a.x = fmaf(c, m.x, a.x);
                a.y = fmaf(c, m.y, a.y);
                a.z = fmaf(c, m.z, a.z);
                a.w = fmaf(c, m.w, a.w);
            }
            hp[q][d4] = a;
        }
        __syncthreads();

        if (tid < DD) {
            const int f4 = tid >> 2, el = tid & 3;
            float s = b1[tid];
            #pragma unroll
            for (int q = 0; q < 8; q++) {
                const float4 p = hp[q][f4];
                s += (el == 0) ? p.x : (el == 1) ? p.y : (el == 2) ? p.z : p.w;
            }
            h_s[tid] = fmaxf(s, 0.0f);
        }
        __syncthreads();

        // --- layer 2: first 8 k from prefetched regs, next 8 loaded now ---
        {
            float4 acc0 = make_float4(0.f, 0.f, 0.f, 0.f);
            float4 acc1 = make_float4(0.f, 0.f, 0.f, 0.f);

            // issue second-half loads immediately (drain during first-half FMAs)
            float4 w2[8];
            #pragma unroll
            for (int j = 0; j < 8; j++)
                w2[j] = W2v[(kg * 16 + 8 + j) * (DD / 4) + cf4];

            #pragma unroll
            for (int j = 0; j < 8; j++) {
                const float s = h_s[kg * 16 + j];
                acc0.x = fmaf(s, w[j].x, acc0.x);
                acc0.y = fmaf(s, w[j].y, acc0.y);
                acc0.z = fmaf(s, w[j].z, acc0.z);
                acc0.w = fmaf(s, w[j].w, acc0.w);
            }
            #pragma unroll
            for (int j = 0; j < 8; j++) {
                const float s = h_s[kg * 16 + 8 + j];
                acc1.x = fmaf(s, w2[j].x, acc1.x);
                acc1.y = fmaf(s, w2[j].y, acc1.y);
                acc1.z = fmaf(s, w2[j].z, acc1.z);
                acc1.w = fmaf(s, w2[j].w, acc1.w);
            }
            acc0.x += acc1.x; acc0.y += acc1.y; acc0.z += acc1.z; acc0.w += acc1.w;
            p2[kg][lane] = acc0;
        }
        __syncthreads();

        if (tid < 32) {
            float4 s = make_float4(0.f, 0.f, 0.f, 0.f);
            #pragma unroll
            for (int g2 = 0; g2 < 16; g2++) {
                const float4 p = p2[g2][tid];
                s.x += p.x; s.y += p.y; s.z += p.z; s.w += p.w;
            }
            const float4 bb = ((const float4*)b2)[half * 32 + tid];
            s.x = fmaxf(s.x + bb.x, 0.f);
            s.y = fmaxf(s.y + bb.y, 0.f);
            s.z = fmaxf(s.z + bb.z, 0.f);
            s.w = fmaxf(s.w + bb.w, 0.f);
            *((float4*)&out[r * DD + half * 128 + 4 * tid]) = s;
        }
    }
}

extern "C" void kernel_launch(void* const* d_in, const int* in_sizes, int n_in,
                              void* d_out, int out_size)
{
    const int*   X    = (const int*)d_in[0];
    const int*   vlen = (const int*)d_in[1];
    const float* emb  = (const float*)d_in[2];
    const float* W1   = (const float*)d_in[3];
    const float* b1   = (const float*)d_in[4];
    const float* W2   = (const float*)d_in[5];
    const float* b2   = (const float*)d_in[6];
    float*       out  = (float*)d_out;

    void* args[] = { (void*)&X, (void*)&vlen, (void*)&emb, (void*)&W1,
                     (void*)&b1, (void*)&W2, (void*)&b2, (void*)&out };
    cudaLaunchCooperativeKernel((void*)prot_net_coop,
                                dim3(GRID), dim3(NT), args, 0, (cudaStream_t)0);
}